// round 13
// baseline (speedup 1.0000x reference)
#include <cuda_runtime.h>
#include <math.h>

#define NT 256
typedef unsigned long long u64;

// f32x2 packed math (Blackwell)
#define FMA2(d,a,b)  asm("fma.rn.f32x2 %0, %1, %2, %0;" : "+l"(d) : "l"(a), "l"(b))
#define UNPK(lo,hi,p) asm("mov.b64 {%0,%1}, %2;" : "=f"(lo), "=f"(hi) : "l"(p))
#define PK(p,lo,hi)   asm("mov.b64 %0, {%1,%2};" : "=l"(p) : "f"(lo), "f"(hi))

// ---------------- device scratch ----------------
__device__ __align__(16) float g_geo[4096];
__device__ __align__(16) float g_p16[4096];
__device__ __align__(16) float g_wq[4096];    // intermediates (in_w-folded)
__device__ __align__(16) float g_wk[4096];
__device__ __align__(16) float g_wv[4096];
__device__ __align__(16) float g_bq[64];
__device__ __align__(16) float g_bk[64];
__device__ __align__(16) float g_bv[64];
// pm2-folded, k-major packed for 1-line global b-loads: [(kb*8+j)*32 + j0*4 + t]
__device__ __align__(16) float g_wqT[4096];
__device__ __align__(16) float g_wkT[4096];
__device__ __align__(16) float g_wvT[4096];
__device__ __align__(16) float g_pm2T[4096];
__device__ __align__(16) float g_bq2[64];
__device__ __align__(16) float g_bk2[64];
__device__ __align__(16) float g_bv2[64];
// conv weights, channel-pair records
__device__ __align__(16) float g_cw1p[16384];
__device__ __align__(16) float g_cw2p[4096];

// ---------------- prep1: geo, P16, eff QKV, conv packs ----------------
__global__ void esa_prep_kernel(const float* __restrict__ points,
                                const int*   __restrict__ adjacency,
                                const float* __restrict__ in_w,
                                const float* __restrict__ in_b,
                                const float* __restrict__ pattern,
                                const float* __restrict__ pm1_w,
                                const float* __restrict__ pm1_b,
                                const float* __restrict__ conv1_w,
                                const float* __restrict__ conv2_w,
                                const float* __restrict__ q_w, const float* __restrict__ q_b,
                                const float* __restrict__ k_w, const float* __restrict__ k_b,
                                const float* __restrict__ v_w, const float* __restrict__ v_b)
{
    const int gtid = blockIdx.x * blockDim.x + threadIdx.x;
    const int gstride = gridDim.x * blockDim.x;
    // 1/sqrt(8) * log2(e): fold softmax scale AND exp->exp2 conversion into Q
    const float scale = 0.3535533905932738f * 1.4426950408889634f;

    for (int idx = gtid; idx < 4096; idx += gstride) {
        int n = idx >> 6, m = idx & 63;
        float dx = points[n*3+0] - points[m*3+0];
        float dy = points[n*3+1] - points[m*3+1];
        float dz = points[n*3+2] - points[m*3+2];
        float dist = sqrtf(dx*dx + dy*dy + dz*dz + 1e-12f);
        g_geo[idx] = (adjacency[idx] > 0) ? 0.5f : (-0.1f / (1.0f + dist));
    }
    for (int idx = gtid; idx < 4096; idx += gstride) {
        int n = idx >> 6, j = idx & 63;
        float s = pm1_b[j];
        const float* wr = pm1_w + j*80 + 64;
        const float* pr = pattern + n*16;
        #pragma unroll
        for (int p = 0; p < 16; p++) s += pr[p] * wr[p];
        g_p16[idx] = s;
    }
    // conv weight pair records
    for (int idx = gtid; idx < 16384; idx += gstride) {
        int j  = idx & 15;
        int o2 = (idx >> 4) & 7;
        int c2 = (idx >> 7) & 31;
        int s  = idx >> 12;
        float v = 0.f;
        if (j < 12) {
            int half = j / 6, jj = j % 6;
            int t = jj >> 1, hb = jj & 1;
            int c = 2*c2 + half;
            int o = o2 + 8*hb;
            v = conv1_w[((s*16 + o)*64 + c)*3 + t];
        }
        g_cw1p[idx] = v;
    }
    for (int idx = gtid; idx < 4096; idx += gstride) {
        int j  = idx & 15;
        int o2 = (idx >> 4) & 7;
        int c2 = (idx >> 7) & 7;
        int s  = idx >> 10;
        float v = 0.f;
        if (j < 12) {
            int half = j / 6, jj = j % 6;
            int t = jj >> 1, hb = jj & 1;
            int c = 2*c2 + half;
            int o = o2 + 8*hb;
            v = conv2_w[((s*16 + o)*16 + c)*3 + t];
        }
        g_cw2p[idx] = v;
    }
    // eff QKV = in_w-slice @ {q,k,v}_w  (Q scaled)
    for (int idx = gtid; idx < 3*4096; idx += gstride) {
        int which = idx >> 12;
        int o = (idx >> 6) & 63;
        int u = idx & 63;
        const float* wi = in_w + which*4096 + o*64;
        const float* wx = (which==0) ? q_w : (which==1) ? k_w : v_w;
        float s = 0.f;
        #pragma unroll 4
        for (int t = 0; t < 64; t++) s += wi[t] * wx[t*64 + u];
        if (which == 0) s *= scale;
        float* dst = (which==0) ? g_wq : (which==1) ? g_wk : g_wv;
        dst[o*64 + u] = s;
    }
    for (int idx = gtid; idx < 192; idx += gstride) {
        int which = idx >> 6, o = idx & 63;
        const float* wi = in_w + which*4096 + o*64;
        const float* bx = (which==0) ? q_b : (which==1) ? k_b : v_b;
        float s = in_b[which*64 + o];
        for (int t = 0; t < 64; t++) s += wi[t] * bx[t];
        if (which == 0) s *= scale;
        float* dst = (which==0) ? g_bq : (which==1) ? g_bk : g_bv;
        dst[o] = s;
    }
}

// ---------------- prep2: fold pm2 into QKV, pack k-major ----------------
__global__ void esa_prep2_kernel(const float* __restrict__ pm2_w,
                                 const float* __restrict__ pm2_b)
{
    const int gtid = blockIdx.x * blockDim.x + threadIdx.x;
    const int gstride = gridDim.x * blockDim.x;

    // W'[o][c] = sum_j W_eff[o][j] * pm2_w[j][c], packed at [(kb*8+j)*32+j0*4+t]
    for (int idx = gtid; idx < 3*4096; idx += gstride) {
        int which = idx >> 12;
        int r = idx & 4095;
        int t  = r & 3;
        int j0 = (r >> 2) & 7;
        int jg = (r >> 5) & 7;
        int kb = r >> 8;
        int o = j0 + 8*jg;
        int c = kb*4 + t;
        const float* we = (which==0) ? g_wq : (which==1) ? g_wk : g_wv;
        float s = 0.f;
        #pragma unroll 4
        for (int u = 0; u < 64; u++) s += we[o*64 + u] * pm2_w[u*64 + c];
        float* dst = (which==0) ? g_wqT : (which==1) ? g_wkT : g_wvT;
        dst[r] = s;
    }
    // b'[o] = W_eff[o][:]·pm2_b + b_eff[o]
    for (int idx = gtid; idx < 192; idx += gstride) {
        int which = idx >> 6, o = idx & 63;
        const float* we = (which==0) ? g_wq : (which==1) ? g_wk : g_wv;
        float s = ((which==0) ? g_bq : (which==1) ? g_bk : g_bv)[o];
        for (int j = 0; j < 64; j++) s += we[o*64 + j] * pm2_b[j];
        float* dst = (which==0) ? g_bq2 : (which==1) ? g_bk2 : g_bv2;
        dst[o] = s;
    }
    // pm2 itself, packed k-major
    for (int idx = gtid; idx < 4096; idx += gstride) {
        int t  = idx & 3;
        int j0 = (idx >> 2) & 7;
        int jg = (idx >> 5) & 7;
        int kb = idx >> 8;
        g_pm2T[idx] = pm2_w[(j0 + 8*jg)*64 + kb*4 + t];
    }
}

// ---------------- weight staging ----------------
__device__ __forceinline__ void pre_ld(const float* __restrict__ src, int sstr,
                                       float4* r, int tid) {
    #pragma unroll
    for (int i = 0; i < 4; i++) {
        int idx4 = tid + i*NT;
        int rr = idx4 >> 4, cc = (idx4 & 15) << 2;
        r[i] = __ldg((const float4*)(src + rr*sstr + cc));
    }
}
__device__ __forceinline__ void pre_st(float* __restrict__ Wd, const float4* r, int tid) {
    #pragma unroll
    for (int i = 0; i < 4; i++) {
        int idx4 = tid + i*NT;
        int rr = idx4 >> 4, cc = (idx4 & 15) << 2;
        *(float4*)(Wd + rr*68 + cc) = r[i];
    }
}
__device__ __forceinline__ void stage_w_half(const float* __restrict__ src,
                                             float* __restrict__ Wd, int t2) {
    float4 r[8];
    #pragma unroll
    for (int i = 0; i < 8; i++) {
        int idx4 = t2 + i*128;
        int rr = idx4 >> 4, cc = (idx4 & 15) << 2;
        r[i] = __ldg((const float4*)(src + rr*64 + cc));
    }
    #pragma unroll
    for (int i = 0; i < 8; i++) {
        int idx4 = t2 + i*128;
        int rr = idx4 >> 4, cc = (idx4 & 15) << 2;
        *(float4*)(Wd + rr*68 + cc) = r[i];
    }
}

// ---------------- f32x2 GEMM, 4x8 tiles on 128 threads, smem weights ----------------
template<bool RELU, bool BIASMAT>
__device__ __forceinline__ void gemm48(const float* __restrict__ in, int sin,
                                       const float* __restrict__ W,
                                       const float* __restrict__ bias,
                                       float* __restrict__ outp, int so, int tid)
{
    const int r  = tid >> 3;
    const int j0 = tid & 7;
    u64 acc[4][8];
    #pragma unroll
    for (int i = 0; i < 4; i++)
        #pragma unroll
        for (int j = 0; j < 8; j++) acc[i][j] = 0ull;

    const float* ap = in + r*sin;
    const float* wp = W + j0*68;
    #pragma unroll 4
    for (int k = 0; k < 64; k += 4) {
        ulonglong2 a[4];
        a[0] = *(const ulonglong2*)(ap + k);
        a[1] = *(const ulonglong2*)(ap + 16*sin + k);
        a[2] = *(const ulonglong2*)(ap + 32*sin + k);
        a[3] = *(const ulonglong2*)(ap + 48*sin + k);
        #pragma unroll
        for (int j = 0; j < 8; j++) {
            ulonglong2 b = *(const ulonglong2*)(wp + j*8*68 + k);
            #pragma unroll
            for (int i = 0; i < 4; i++) {
                FMA2(acc[i][j], a[i].x, b.x);
                FMA2(acc[i][j], a[i].y, b.y);
            }
        }
    }
    #pragma unroll
    for (int j = 0; j < 8; j++) {
        int jj = j0 + 8*j;
        float bj = BIASMAT ? 0.f : __ldg(bias + jj);
        #pragma unroll
        for (int i = 0; i < 4; i++) {
            int row = r + 16*i;
            float lo, hi; UNPK(lo, hi, acc[i][j]);
            float v = lo + hi + bj;
            if (BIASMAT) v += __ldg(bias + row*64 + jj);
            if (RELU) v = fmaxf(v, 0.f);
            outp[row*so + jj] = v;
        }
    }
}

// ---------------- GEMM with k-major packed GLOBAL weights (1 line per load) ------
__device__ __forceinline__ void gemm48g(const float* __restrict__ in, int sin,
                                        const float* __restrict__ Wg,
                                        const float* __restrict__ bias,
                                        float* __restrict__ outp, int so, int t)
{
    const int r  = t >> 3;
    const int j0 = t & 7;
    u64 acc[4][8];
    #pragma unroll
    for (int i = 0; i < 4; i++)
        #pragma unroll
        for (int j = 0; j < 8; j++) acc[i][j] = 0ull;

    const float* ap = in + r*sin;
    const float* wp = Wg + j0*4;
    #pragma unroll 4
    for (int kb = 0; kb < 16; kb++) {
        int k = kb*4;
        ulonglong2 a[4];
        a[0] = *(const ulonglong2*)(ap + k);
        a[1] = *(const ulonglong2*)(ap + 16*sin + k);
        a[2] = *(const ulonglong2*)(ap + 32*sin + k);
        a[3] = *(const ulonglong2*)(ap + 48*sin + k);
        #pragma unroll
        for (int j = 0; j < 8; j++) {
            ulonglong2 b = __ldg((const ulonglong2*)(wp + (kb*8 + j)*32));
            #pragma unroll
            for (int i = 0; i < 4; i++) {
                FMA2(acc[i][j], a[i].x, b.x);
                FMA2(acc[i][j], a[i].y, b.y);
            }
        }
    }
    #pragma unroll
    for (int j = 0; j < 8; j++) {
        int jj = j0 + 8*j;
        float bj = __ldg(bias + jj);
        #pragma unroll
        for (int i = 0; i < 4; i++) {
            int row = r + 16*i;
            float lo, hi; UNPK(lo, hi, acc[i][j]);
            outp[row*so + jj] = lo + hi + bj;
        }
    }
}

// mo projection + geo + residual + FUSED LayerNorm
__device__ __forceinline__ void gemm_mo_ln48(const float* __restrict__ in,
                                             const float* __restrict__ W,
                                             const float* __restrict__ mo_b,
                                             const float* __restrict__ pf,
                                             const float* __restrict__ LNS,
                                             float* __restrict__ outp, int tid)
{
    const int r  = tid >> 3;
    const int j0 = tid & 7;
    u64 acc[4][8];
    #pragma unroll
    for (int i = 0; i < 4; i++)
        #pragma unroll
        for (int j = 0; j < 8; j++) acc[i][j] = 0ull;

    const float* ap = in + r*68;
    const float* wp = W + j0*68;
    #pragma unroll 4
    for (int k = 0; k < 64; k += 4) {
        ulonglong2 a[4];
        a[0] = *(const ulonglong2*)(ap + k);
        a[1] = *(const ulonglong2*)(ap + 16*68 + k);
        a[2] = *(const ulonglong2*)(ap + 32*68 + k);
        a[3] = *(const ulonglong2*)(ap + 48*68 + k);
        #pragma unroll
        for (int j = 0; j < 8; j++) {
            ulonglong2 b = *(const ulonglong2*)(wp + j*8*68 + k);
            #pragma unroll
            for (int i = 0; i < 4; i++) {
                FMA2(acc[i][j], a[i].x, b.x);
                FMA2(acc[i][j], a[i].y, b.y);
            }
        }
    }
    #pragma unroll
    for (int i = 0; i < 4; i++) {
        int row = r + 16*i;
        float v[8];
        float rs = 0.f, rq = 0.f;
        #pragma unroll
        for (int j = 0; j < 8; j++) {
            int jj = j0 + 8*j;
            float lo, hi; UNPK(lo, hi, acc[i][j]);
            float t = lo + hi + __ldg(mo_b + jj) + __ldg(g_geo + row*64 + jj)
                    + pf[row*68 + jj];
            v[j] = t; rs += t; rq += t*t;
        }
        rs += __shfl_xor_sync(0xffffffffu, rs, 1);
        rq += __shfl_xor_sync(0xffffffffu, rq, 1);
        rs += __shfl_xor_sync(0xffffffffu, rs, 2);
        rq += __shfl_xor_sync(0xffffffffu, rq, 2);
        rs += __shfl_xor_sync(0xffffffffu, rs, 4);
        rq += __shfl_xor_sync(0xffffffffu, rq, 4);
        float mu  = rs * 0.015625f;
        float var = rq * 0.015625f - mu*mu;
        float ri = rsqrtf(var + 1e-5f);
        #pragma unroll
        for (int j = 0; j < 8; j++) {
            int jj = j0 + 8*j;
            outp[row*68 + jj] = (v[j] - mu) * ri * LNS[jj] + LNS[64 + jj];
        }
    }
}

__device__ __forceinline__ void gemm_out48(const float* __restrict__ in,
                                           const float* __restrict__ W,
                                           const float* __restrict__ bias,
                                           float* __restrict__ og, int tid)
{
    const int r  = tid >> 3;
    const int j0 = tid & 7;
    u64 acc[4][8];
    #pragma unroll
    for (int i = 0; i < 4; i++)
        #pragma unroll
        for (int j = 0; j < 8; j++) acc[i][j] = 0ull;

    const float* ap = in + r*68;
    const float* wp = W + j0*68;
    #pragma unroll 4
    for (int k = 0; k < 64; k += 4) {
        ulonglong2 a[4];
        a[0] = *(const ulonglong2*)(ap + k);
        a[1] = *(const ulonglong2*)(ap + 16*68 + k);
        a[2] = *(const ulonglong2*)(ap + 32*68 + k);
        a[3] = *(const ulonglong2*)(ap + 48*68 + k);
        #pragma unroll
        for (int j = 0; j < 8; j++) {
            ulonglong2 b = *(const ulonglong2*)(wp + j*8*68 + k);
            #pragma unroll
            for (int i = 0; i < 4; i++) {
                FMA2(acc[i][j], a[i].x, b.x);
                FMA2(acc[i][j], a[i].y, b.y);
            }
        }
    }
    #pragma unroll
    for (int j = 0; j < 8; j++) {
        int jj = j0 + 8*j;
        float bj = __ldg(bias + jj);
        #pragma unroll
        for (int i = 0; i < 4; i++) {
            int row = r + 16*i;
            float lo, hi; UNPK(lo, hi, acc[i][j]);
            og[jj*64 + row] = lo + hi + bj;
        }
    }
}

// splat a 10-float window into packed pairs
#define SPLAT10(XR, sp) { \
    float4 v0 = *(const float4*)(XR); \
    float4 v1 = *(const float4*)((XR)+4); \
    float2 v2 = *(const float2*)((XR)+8); \
    PK(sp[0],v0.x,v0.x); PK(sp[1],v0.y,v0.y); PK(sp[2],v0.z,v0.z); PK(sp[3],v0.w,v0.w); \
    PK(sp[4],v1.x,v1.x); PK(sp[5],v1.y,v1.y); PK(sp[6],v1.z,v1.z); PK(sp[7],v1.w,v1.w); \
    PK(sp[8],v2.x,v2.x); PK(sp[9],v2.y,v2.y); }

// conv channel-pair step: weights pre-paired (o2,o2+8) -> direct u64 operands
#define CONV_PAIR(XR0, XR1, WT) { \
    ulonglong2 L0 = __ldg((const ulonglong2*)(WT)); \
    ulonglong2 L1 = __ldg((const ulonglong2*)((WT)+4)); \
    ulonglong2 L2 = __ldg((const ulonglong2*)((WT)+8)); \
    u64 sp[10]; \
    SPLAT10(XR0, sp); \
    _Pragma("unroll") \
    for (int ii = 0; ii < 8; ii++) { \
        FMA2(a[ii], L0.x, sp[ii]); FMA2(a[ii], L0.y, sp[ii+1]); FMA2(a[ii], L1.x, sp[ii+2]); } \
    SPLAT10(XR1, sp); \
    _Pragma("unroll") \
    for (int ii = 0; ii < 8; ii++) { \
        FMA2(a[ii], L1.y, sp[ii]); FMA2(a[ii], L2.x, sp[ii+1]); FMA2(a[ii], L2.y, sp[ii+2]); } }

// ---------------- main fused kernel: one CTA per batch element ----------------
// smem (floats): X 0(4352) | CB 4352(4352) | T 8704(4352) | PF 13056(4352)
//                | W0 17408(4352) | W1 21760(4352; aliased as 4x Y1 during conv)
//                | LNS 26112(128)
#define SMEM_FLOATS 26240

__global__ void __launch_bounds__(NT, 2)
esa_main_kernel(const float* __restrict__ x,
                const float* __restrict__ conv1_b, const float* __restrict__ conv2_b,
                const float* __restrict__ pm1_w,  const float* __restrict__ pm2_b,
                const float* __restrict__ mo_w,   const float* __restrict__ mo_b,
                const float* __restrict__ out_w,  const float* __restrict__ out_b,
                const float* __restrict__ ln_g,   const float* __restrict__ ln_b,
                float* __restrict__ out)
{
    extern __shared__ float sm[];
    const int tid = threadIdx.x;
    const int b = blockIdx.x;
    float* X   = sm;
    float* CB  = sm + 4352;
    float* T   = sm + 8704;
    float* PF  = sm + 13056;
    float* W0  = sm + 17408;
    float* W1  = sm + 21760;
    float* LNS = sm + 26112;

    // ---- load x + stage pm1 into W0 + stage ln params ----
    {
        float4 pw[4]; pre_ld(pm1_w, 80, pw, tid);
        const float* xg = x + (size_t)b * 4096;
        for (int idx4 = tid; idx4 < 1024; idx4 += NT) {
            float4 v = __ldg((const float4*)xg + idx4);
            int c = idx4 >> 4, n = (idx4 & 15) << 2;
            float* rr = X + c*68 + 1 + n;
            rr[0] = v.x; rr[1] = v.y; rr[2] = v.z; rr[3] = v.w;
        }
        pre_st(W0, pw, tid);
        if (tid < 64) {
            X[tid*68] = 0.f;  X[tid*68 + 65] = 0.f;    // x pads
            W1[tid*68] = 0.f; W1[tid*68 + 65] = 0.f;   // Y1 pads (4 scales x 16 rows)
            LNS[tid]      = __ldg(ln_g + tid);
            LNS[64 + tid] = __ldg(ln_b + tid);
        }
    }
    __syncthreads();

    // ---- conv stack: 4 scales in one pass; thread = (s, o2, nq), 2 out-ch each ----
    {
        const int s  = tid >> 6;
        const int o2 = (tid >> 3) & 7;
        const int nq = tid & 7;
        const int base = nq * 8;
        float* Y1 = W1 + s*1088;
        {   // conv1: 64 -> 16 channels (channel pairs)
            const float* wt = g_cw1p + ((s*32)*8 + o2)*16;
            u64 a[8];
            #pragma unroll
            for (int j = 0; j < 8; j++) a[j] = 0ull;
            #pragma unroll 2
            for (int c2 = 0; c2 < 32; c2++)
                CONV_PAIR(X + (2*c2)*68 + base, X + (2*c2+1)*68 + base, wt + c2*128);
            float bb0 = __ldg(conv1_b + s*16 + o2);
            float bb1 = __ldg(conv1_b + s*16 + o2 + 8);
            float* y0 = Y1 + o2*68 + 1 + base;
            float* y1r = Y1 + (o2+8)*68 + 1 + base;
            #pragma unroll
            for (int j = 0; j < 8; j++) {
                float lo, hi; UNPK(lo, hi, a[j]);
                y0[j]  = fmaxf(lo+bb0, 0.f);
                y1r[j] = fmaxf(hi+bb1, 0.f);
            }
        }
        __syncthreads();
        {   // conv2: 16 -> 16 channels, swizzled transposed store into CB
            const float* wt = g_cw2p + ((s*8)*8 + o2)*16;
            u64 a[8];
            #pragma unroll
            for (int j = 0; j < 8; j++) a[j] = 0ull;
            #pragma unroll
            for (int c2 = 0; c2 < 8; c2++)
                CONV_PAIR(Y1 + (2*c2)*68 + base, Y1 + (2*c2+1)*68 + base, wt + c2*128);
            float bb0 = __ldg(conv2_b + s*16 + o2);
            float bb1 = __ldg(conv2_b + s*16 + o2 + 8);
            float olo[8], ohi[8];
            #pragma unroll
            for (int j = 0; j < 8; j++) UNPK(olo[j], ohi[j], a[j]);
            int ch0 = s*16 + o2, ch1 = ch0 + 8;
            #pragma unroll
            for (int ii = 0; ii < 8; ii++) {
                int rr = (ii + nq) & 7;     // bank-conflict-free rotation
                CB[(base+rr)*68 + ch0] = fmaxf(olo[rr]+bb0, 0.f);
                CB[(base+rr)*68 + ch1] = fmaxf(ohi[rr]+bb1, 0.f);
            }
        }
        __syncthreads();
    }

    // ---- P1: pm1 (W0): CB -> T (relu, P16 bias); stagers: mo -> W1 ----
    if (tid < 128) gemm48<true, true>(CB, 68, W0, g_p16, T, 68, tid);
    else stage_w_half(mo_w, W1, tid - 128);
    __syncthreads();

    // ---- P2: Q || K (pm2-folded, global k-major weights), all 8 warps ----
    if (tid < 128) gemm48g(T, 68, g_wqT, g_bq2, CB, 68, tid);       // Q -> CB
    else           gemm48g(T, 68, g_wkT, g_bk2, X,  68, tid - 128); // K -> X
    __syncthreads();

    // ---- P3: V || pm2, all 8 warps ----
    if (tid < 128) gemm48g(T, 68, g_wvT, g_bv2, PF, 68, tid);       // V  -> PF
    else           gemm48g(T, 68, g_pm2T, pm2_b, W0, 68, tid - 128);// pf -> W0
    __syncthreads();

    // ---- P4: attention (Q=CB, K=X, V=PF), exp2 (log2e folded into Q) ----
    {
        const int h8 = (tid >> 5) * 8;
        const int n0 = tid & 31;
        const float* q0p = CB + n0*68 + h8;
        const float* q1p = q0p + 32*68;
        ulonglong2 qa0 = *(const ulonglong2*)q0p;
        ulonglong2 qb0 = *(const ulonglong2*)(q0p + 4);
        ulonglong2 qa1 = *(const ulonglong2*)q1p;
        ulonglong2 qb1 = *(const ulonglong2*)(q1p + 4);
        float su0 = 0.f, su1 = 0.f;
        u64 c0[4] = {0ull,0ull,0ull,0ull};
        u64 c1[4] = {0ull,0ull,0ull,0ull};
        #pragma unroll 4
        for (int m = 0; m < 64; m++) {
            const float* kr = X  + m*68 + h8;
            const float* vr = PF + m*68 + h8;
            ulonglong2 ka = *(const ulonglong2*)kr;
            ulonglong2 kb = *(const ulonglong2*)(kr + 4);
            ulonglong2 va = *(const ulonglong2*)vr;
            ulonglong2 vb = *(const ulonglong2*)(vr + 4);
            u64 d0 = 0ull, d1 = 0ull;
            FMA2(d0, qa0.x, ka.x); FMA2(d0, qa0.y, ka.y);
            FMA2(d0, qb0.x, kb.x); FMA2(d0, qb0.y, kb.y);
            FMA2(d1, qa1.x, ka.x); FMA2(d1, qa1.y, ka.y);
            FMA2(d1, qb1.x, kb.x); FMA2(d1, qb1.y, kb.y);
            float lo, hi;
            UNPK(lo, hi, d0); float e0 = exp2f(lo + hi);
            UNPK(lo, hi, d1); float e1 = exp2f(lo + hi);
            su0 += e0; su1 += e1;
            u64 e0p, e1p;
            PK(e0p, e0, e0); PK(e1p, e1, e1);
            FMA2(c0[0], e0p, va.x); FMA2(c0[1], e0p, va.y);
            FMA2(c0[2], e0p, vb.x); FMA2(c0[3], e0p, vb.y);
            FMA2(c1[0], e1p, va.x); FMA2(c1[1], e1p, va.y);
            FMA2(c1[2], e1p, vb.x); FMA2(c1[3], e1p, vb.y);
        }
        float inv0 = 1.f / su0, inv1 = 1.f / su1;
        float w0l,w0h,w1l,w1h,w2l,w2h,w3l,w3h;
        UNPK(w0l,w0h,c0[0]); UNPK(w1l,w1h,c0[1]); UNPK(w2l,w2h,c0[2]); UNPK(w3l,w3h,c0[3]);
        *(float4*)(CB + n0*68 + h8)     = make_float4(w0l*inv0, w0h*inv0, w1l*inv0, w1h*inv0);
        *(float4*)(CB + n0*68 + h8 + 4) = make_float4(w2l*inv0, w2h*inv0, w3l*inv0, w3h*inv0);
        UNPK(w0l,w0h,c1[0]); UNPK(w1l,w1h,c1[1]); UNPK(w2l,w2h,c1[2]); UNPK(w3l,w3h,c1[3]);
        *(float4*)(CB + (n0+32)*68 + h8)     = make_float4(w0l*inv1, w0h*inv1, w1l*inv1, w1h*inv1);
        *(float4*)(CB + (n0+32)*68 + h8 + 4) = make_float4(w2l*inv1, w2h*inv1, w3l*inv1, w3h*inv1);
    }
    __syncthreads();

    // ---- P5: mo (W1) + geo + residual(pf=W0) + fused LN; stagers: out_w -> X ----
    if (tid < 128) gemm_mo_ln48(CB, W1, mo_b, W0, LNS, T, tid);
    else stage_w_half(out_w, X, tid - 128);
    __syncthreads();

    // ---- P6: final projection (X): T -> global, transposed layout ----
    if (tid < 128) gemm_out48(T, X, out_b, out + (size_t)b * 4096, tid);
}

// ---------------- launch ----------------
extern "C" void kernel_launch(void* const* d_in, const int* in_sizes, int n_in,
                              void* d_out, int out_size)
{
    const float* x         = (const float*)d_in[0];
    const float* points    = (const float*)d_in[1];
    const float* conv1_w   = (const float*)d_in[2];
    const float* conv1_b   = (const float*)d_in[3];
    const float* conv2_w   = (const float*)d_in[4];
    const float* conv2_b   = (const float*)d_in[5];
    const float* pattern   = (const float*)d_in[6];
    const float* pm1_w     = (const float*)d_in[7];
    const float* pm1_b     = (const float*)d_in[8];
    const float* pm2_w     = (const float*)d_in[9];
    const float* pm2_b     = (const float*)d_in[10];
    const float* q_w       = (const float*)d_in[11];
    const float* q_b       = (const float*)d_in[12];
    const float* k_w       = (const float*)d_in[13];
    const float* k_b       = (const float*)d_in[14];
    const float* v_w       = (const float*)d_in[15];
    const float* v_b       = (const float*)d_in[16];
    const float* in_w      = (const float*)d_in[17];
    const float* in_b      = (const float*)d_in[18];
    const float* mo_w      = (const float*)d_in[19];
    const float* mo_b      = (const float*)d_in[20];
    const float* out_w     = (const float*)d_in[21];
    const float* out_b     = (const float*)d_in[22];
    const float* ln_g      = (const float*)d_in[23];
    const float* ln_b      = (const float*)d_in[24];
    const int*   adjacency = (const int*)d_in[25];

    int B = in_sizes[0] / 4096;
    size_t smem = SMEM_FLOATS * sizeof(float);
    cudaFuncSetAttribute(esa_main_kernel, cudaFuncAttributeMaxDynamicSharedMemorySize, (int)smem);

    esa_prep_kernel<<<24, NT>>>(points, adjacency, in_w, in_b, pattern, pm1_w, pm1_b,
                                conv1_w, conv2_w,
                                q_w, q_b, k_w, k_b, v_w, v_b);
    esa_prep2_kernel<<<24, NT>>>(pm2_w, pm2_b);
    esa_main_kernel<<<B, NT, smem>>>(x, conv1_b, conv2_b,
                                     pm1_w, pm2_b, mo_w, mo_b,
                                     out_w, out_b, ln_g, ln_b, (float*)d_out);
}

// round 14
// speedup vs baseline: 1.0054x; 1.0054x over previous
#include <cuda_runtime.h>
#include <math.h>

#define NT 256
typedef unsigned long long u64;

// f32x2 packed math (Blackwell)
#define FMA2(d,a,b)  asm("fma.rn.f32x2 %0, %1, %2, %0;" : "+l"(d) : "l"(a), "l"(b))
#define UNPK(lo,hi,p) asm("mov.b64 {%0,%1}, %2;" : "=f"(lo), "=f"(hi) : "l"(p))
#define PK(p,lo,hi)   asm("mov.b64 %0, {%1,%2};" : "=l"(p) : "f"(lo), "f"(hi))

// ---------------- device scratch ----------------
__device__ __align__(16) float g_geo[4096];
__device__ __align__(16) float g_p16[4096];
__device__ __align__(16) float g_wq[4096];    // intermediates (in_w-folded)
__device__ __align__(16) float g_wk[4096];
__device__ __align__(16) float g_wv[4096];
__device__ __align__(16) float g_bq[64];
__device__ __align__(16) float g_bk[64];
__device__ __align__(16) float g_bv[64];
// pm2-folded, k-major packed for 1-line global b-loads: [(kb*8+j)*32 + j0*4 + t]
__device__ __align__(16) float g_wqT[4096];
__device__ __align__(16) float g_wkT[4096];
__device__ __align__(16) float g_wvT[4096];
__device__ __align__(16) float g_pm2T[4096];
__device__ __align__(16) float g_bq2[64];
__device__ __align__(16) float g_bk2[64];
__device__ __align__(16) float g_bv2[64];
// conv weights, channel-pair records
__device__ __align__(16) float g_cw1p[16384];
__device__ __align__(16) float g_cw2p[4096];

// ---------------- prep1: geo, P16, eff QKV, conv packs ----------------
__global__ void esa_prep_kernel(const float* __restrict__ points,
                                const int*   __restrict__ adjacency,
                                const float* __restrict__ in_w,
                                const float* __restrict__ in_b,
                                const float* __restrict__ pattern,
                                const float* __restrict__ pm1_w,
                                const float* __restrict__ pm1_b,
                                const float* __restrict__ conv1_w,
                                const float* __restrict__ conv2_w,
                                const float* __restrict__ q_w, const float* __restrict__ q_b,
                                const float* __restrict__ k_w, const float* __restrict__ k_b,
                                const float* __restrict__ v_w, const float* __restrict__ v_b)
{
    const int gtid = blockIdx.x * blockDim.x + threadIdx.x;
    const int gstride = gridDim.x * blockDim.x;
    // 1/sqrt(8) * log2(e): fold softmax scale AND exp->exp2 conversion into Q
    const float scale = 0.3535533905932738f * 1.4426950408889634f;

    for (int idx = gtid; idx < 4096; idx += gstride) {
        int n = idx >> 6, m = idx & 63;
        float dx = points[n*3+0] - points[m*3+0];
        float dy = points[n*3+1] - points[m*3+1];
        float dz = points[n*3+2] - points[m*3+2];
        float dist = sqrtf(dx*dx + dy*dy + dz*dz + 1e-12f);
        g_geo[idx] = (adjacency[idx] > 0) ? 0.5f : (-0.1f / (1.0f + dist));
    }
    for (int idx = gtid; idx < 4096; idx += gstride) {
        int n = idx >> 6, j = idx & 63;
        float s = __ldg(pm1_b + j);
        const float* wr = pm1_w + j*80 + 64;
        const float* pr = pattern + n*16;
        #pragma unroll
        for (int p = 0; p < 16; p++) s += __ldg(pr + p) * __ldg(wr + p);
        g_p16[idx] = s;
    }
    // conv weight pair records
    for (int idx = gtid; idx < 16384; idx += gstride) {
        int j  = idx & 15;
        int o2 = (idx >> 4) & 7;
        int c2 = (idx >> 7) & 31;
        int s  = idx >> 12;
        float v = 0.f;
        if (j < 12) {
            int half = j / 6, jj = j % 6;
            int t = jj >> 1, hb = jj & 1;
            int c = 2*c2 + half;
            int o = o2 + 8*hb;
            v = __ldg(conv1_w + ((s*16 + o)*64 + c)*3 + t);
        }
        g_cw1p[idx] = v;
    }
    for (int idx = gtid; idx < 4096; idx += gstride) {
        int j  = idx & 15;
        int o2 = (idx >> 4) & 7;
        int c2 = (idx >> 7) & 7;
        int s  = idx >> 10;
        float v = 0.f;
        if (j < 12) {
            int half = j / 6, jj = j % 6;
            int t = jj >> 1, hb = jj & 1;
            int c = 2*c2 + half;
            int o = o2 + 8*hb;
            v = __ldg(conv2_w + ((s*16 + o)*16 + c)*3 + t);
        }
        g_cw2p[idx] = v;
    }
    // eff QKV = in_w-slice @ {q,k,v}_w  (Q scaled)
    for (int idx = gtid; idx < 3*4096; idx += gstride) {
        int which = idx >> 12;
        int o = (idx >> 6) & 63;
        int u = idx & 63;
        const float* wi = in_w + which*4096 + o*64;
        const float* wx = (which==0) ? q_w : (which==1) ? k_w : v_w;
        float s = 0.f;
        #pragma unroll 8
        for (int t = 0; t < 64; t++) s += __ldg(wi + t) * __ldg(wx + t*64 + u);
        if (which == 0) s *= scale;
        float* dst = (which==0) ? g_wq : (which==1) ? g_wk : g_wv;
        dst[o*64 + u] = s;
    }
    for (int idx = gtid; idx < 192; idx += gstride) {
        int which = idx >> 6, o = idx & 63;
        const float* wi = in_w + which*4096 + o*64;
        const float* bx = (which==0) ? q_b : (which==1) ? k_b : v_b;
        float s = __ldg(in_b + which*64 + o);
        #pragma unroll 8
        for (int t = 0; t < 64; t++) s += __ldg(wi + t) * __ldg(bx + t);
        if (which == 0) s *= scale;
        float* dst = (which==0) ? g_bq : (which==1) ? g_bk : g_bv;
        dst[o] = s;
    }
}

// ---------------- prep2: fold pm2 into QKV, pack k-major ----------------
__global__ void esa_prep2_kernel(const float* __restrict__ pm2_w,
                                 const float* __restrict__ pm2_b)
{
    const int gtid = blockIdx.x * blockDim.x + threadIdx.x;
    const int gstride = gridDim.x * blockDim.x;

    // W'[o][c] = sum_j W_eff[o][j] * pm2_w[j][c], packed at [(kb*8+j)*32+j0*4+t]
    for (int idx = gtid; idx < 3*4096; idx += gstride) {
        int which = idx >> 12;
        int r = idx & 4095;
        int t  = r & 3;
        int j0 = (r >> 2) & 7;
        int jg = (r >> 5) & 7;
        int kb = r >> 8;
        int o = j0 + 8*jg;
        int c = kb*4 + t;
        const float* we = (which==0) ? g_wq : (which==1) ? g_wk : g_wv;
        float s = 0.f;
        #pragma unroll 8
        for (int u = 0; u < 64; u++) s += we[o*64 + u] * __ldg(pm2_w + u*64 + c);
        float* dst = (which==0) ? g_wqT : (which==1) ? g_wkT : g_wvT;
        dst[r] = s;
    }
    // b'[o] = W_eff[o][:]·pm2_b + b_eff[o]
    for (int idx = gtid; idx < 192; idx += gstride) {
        int which = idx >> 6, o = idx & 63;
        const float* we = (which==0) ? g_wq : (which==1) ? g_wk : g_wv;
        float s = ((which==0) ? g_bq : (which==1) ? g_bk : g_bv)[o];
        #pragma unroll 8
        for (int j = 0; j < 64; j++) s += we[o*64 + j] * __ldg(pm2_b + j);
        float* dst = (which==0) ? g_bq2 : (which==1) ? g_bk2 : g_bv2;
        dst[o] = s;
    }
    // pm2 itself, packed k-major
    for (int idx = gtid; idx < 4096; idx += gstride) {
        int t  = idx & 3;
        int j0 = (idx >> 2) & 7;
        int jg = (idx >> 5) & 7;
        int kb = idx >> 8;
        g_pm2T[idx] = __ldg(pm2_w + (j0 + 8*jg)*64 + kb*4 + t);
    }
}

// ---------------- weight staging ----------------
__device__ __forceinline__ void pre_ld(const float* __restrict__ src, int sstr,
                                       float4* r, int tid) {
    #pragma unroll
    for (int i = 0; i < 4; i++) {
        int idx4 = tid + i*NT;
        int rr = idx4 >> 4, cc = (idx4 & 15) << 2;
        r[i] = __ldg((const float4*)(src + rr*sstr + cc));
    }
}
__device__ __forceinline__ void pre_st(float* __restrict__ Wd, const float4* r, int tid) {
    #pragma unroll
    for (int i = 0; i < 4; i++) {
        int idx4 = tid + i*NT;
        int rr = idx4 >> 4, cc = (idx4 & 15) << 2;
        *(float4*)(Wd + rr*68 + cc) = r[i];
    }
}
__device__ __forceinline__ void stage_w_half(const float* __restrict__ src,
                                             float* __restrict__ Wd, int t2) {
    float4 r[8];
    #pragma unroll
    for (int i = 0; i < 8; i++) {
        int idx4 = t2 + i*128;
        int rr = idx4 >> 4, cc = (idx4 & 15) << 2;
        r[i] = __ldg((const float4*)(src + rr*64 + cc));
    }
    #pragma unroll
    for (int i = 0; i < 8; i++) {
        int idx4 = t2 + i*128;
        int rr = idx4 >> 4, cc = (idx4 & 15) << 2;
        *(float4*)(Wd + rr*68 + cc) = r[i];
    }
}

// ---------------- f32x2 GEMM, 4x8 tiles on 128 threads, smem weights ----------------
template<bool RELU, bool BIASMAT>
__device__ __forceinline__ void gemm48(const float* __restrict__ in, int sin,
                                       const float* __restrict__ W,
                                       const float* __restrict__ bias,
                                       float* __restrict__ outp, int so, int tid)
{
    const int r  = tid >> 3;
    const int j0 = tid & 7;
    u64 acc[4][8];
    #pragma unroll
    for (int i = 0; i < 4; i++)
        #pragma unroll
        for (int j = 0; j < 8; j++) acc[i][j] = 0ull;

    const float* ap = in + r*sin;
    const float* wp = W + j0*68;
    #pragma unroll 4
    for (int k = 0; k < 64; k += 4) {
        ulonglong2 a[4];
        a[0] = *(const ulonglong2*)(ap + k);
        a[1] = *(const ulonglong2*)(ap + 16*sin + k);
        a[2] = *(const ulonglong2*)(ap + 32*sin + k);
        a[3] = *(const ulonglong2*)(ap + 48*sin + k);
        #pragma unroll
        for (int j = 0; j < 8; j++) {
            ulonglong2 b = *(const ulonglong2*)(wp + j*8*68 + k);
            #pragma unroll
            for (int i = 0; i < 4; i++) {
                FMA2(acc[i][j], a[i].x, b.x);
                FMA2(acc[i][j], a[i].y, b.y);
            }
        }
    }
    #pragma unroll
    for (int j = 0; j < 8; j++) {
        int jj = j0 + 8*j;
        float bj = BIASMAT ? 0.f : __ldg(bias + jj);
        #pragma unroll
        for (int i = 0; i < 4; i++) {
            int row = r + 16*i;
            float lo, hi; UNPK(lo, hi, acc[i][j]);
            float v = lo + hi + bj;
            if (BIASMAT) v += __ldg(bias + row*64 + jj);
            if (RELU) v = fmaxf(v, 0.f);
            outp[row*so + jj] = v;
        }
    }
}

// ---------------- GEMM with k-major packed GLOBAL weights (1 line per load) ------
__device__ __forceinline__ void gemm48g(const float* __restrict__ in, int sin,
                                        const float* __restrict__ Wg,
                                        const float* __restrict__ bias,
                                        float* __restrict__ outp, int so, int t)
{
    const int r  = t >> 3;
    const int j0 = t & 7;
    u64 acc[4][8];
    #pragma unroll
    for (int i = 0; i < 4; i++)
        #pragma unroll
        for (int j = 0; j < 8; j++) acc[i][j] = 0ull;

    const float* ap = in + r*sin;
    const float* wp = Wg + j0*4;
    #pragma unroll 4
    for (int kb = 0; kb < 16; kb++) {
        int k = kb*4;
        ulonglong2 a[4];
        a[0] = *(const ulonglong2*)(ap + k);
        a[1] = *(const ulonglong2*)(ap + 16*sin + k);
        a[2] = *(const ulonglong2*)(ap + 32*sin + k);
        a[3] = *(const ulonglong2*)(ap + 48*sin + k);
        #pragma unroll
        for (int j = 0; j < 8; j++) {
            ulonglong2 b = __ldg((const ulonglong2*)(wp + (kb*8 + j)*32));
            #pragma unroll
            for (int i = 0; i < 4; i++) {
                FMA2(acc[i][j], a[i].x, b.x);
                FMA2(acc[i][j], a[i].y, b.y);
            }
        }
    }
    #pragma unroll
    for (int j = 0; j < 8; j++) {
        int jj = j0 + 8*j;
        float bj = __ldg(bias + jj);
        #pragma unroll
        for (int i = 0; i < 4; i++) {
            int row = r + 16*i;
            float lo, hi; UNPK(lo, hi, acc[i][j]);
            outp[row*so + jj] = lo + hi + bj;
        }
    }
}

// mo projection + geo + residual + FUSED LayerNorm
__device__ __forceinline__ void gemm_mo_ln48(const float* __restrict__ in,
                                             const float* __restrict__ W,
                                             const float* __restrict__ mo_b,
                                             const float* __restrict__ pf,
                                             const float* __restrict__ LNS,
                                             float* __restrict__ outp, int tid)
{
    const int r  = tid >> 3;
    const int j0 = tid & 7;
    u64 acc[4][8];
    #pragma unroll
    for (int i = 0; i < 4; i++)
        #pragma unroll
        for (int j = 0; j < 8; j++) acc[i][j] = 0ull;

    const float* ap = in + r*68;
    const float* wp = W + j0*68;
    #pragma unroll 4
    for (int k = 0; k < 64; k += 4) {
        ulonglong2 a[4];
        a[0] = *(const ulonglong2*)(ap + k);
        a[1] = *(const ulonglong2*)(ap + 16*68 + k);
        a[2] = *(const ulonglong2*)(ap + 32*68 + k);
        a[3] = *(const ulonglong2*)(ap + 48*68 + k);
        #pragma unroll
        for (int j = 0; j < 8; j++) {
            ulonglong2 b = *(const ulonglong2*)(wp + j*8*68 + k);
            #pragma unroll
            for (int i = 0; i < 4; i++) {
                FMA2(acc[i][j], a[i].x, b.x);
                FMA2(acc[i][j], a[i].y, b.y);
            }
        }
    }
    #pragma unroll
    for (int i = 0; i < 4; i++) {
        int row = r + 16*i;
        float v[8];
        float rs = 0.f, rq = 0.f;
        #pragma unroll
        for (int j = 0; j < 8; j++) {
            int jj = j0 + 8*j;
            float lo, hi; UNPK(lo, hi, acc[i][j]);
            float t = lo + hi + __ldg(mo_b + jj) + __ldg(g_geo + row*64 + jj)
                    + pf[row*68 + jj];
            v[j] = t; rs += t; rq += t*t;
        }
        rs += __shfl_xor_sync(0xffffffffu, rs, 1);
        rq += __shfl_xor_sync(0xffffffffu, rq, 1);
        rs += __shfl_xor_sync(0xffffffffu, rs, 2);
        rq += __shfl_xor_sync(0xffffffffu, rq, 2);
        rs += __shfl_xor_sync(0xffffffffu, rs, 4);
        rq += __shfl_xor_sync(0xffffffffu, rq, 4);
        float mu  = rs * 0.015625f;
        float var = rq * 0.015625f - mu*mu;
        float ri = rsqrtf(var + 1e-5f);
        #pragma unroll
        for (int j = 0; j < 8; j++) {
            int jj = j0 + 8*j;
            outp[row*68 + jj] = (v[j] - mu) * ri * LNS[jj] + LNS[64 + jj];
        }
    }
}

__device__ __forceinline__ void gemm_out48(const float* __restrict__ in,
                                           const float* __restrict__ W,
                                           const float* __restrict__ bias,
                                           float* __restrict__ og, int tid)
{
    const int r  = tid >> 3;
    const int j0 = tid & 7;
    u64 acc[4][8];
    #pragma unroll
    for (int i = 0; i < 4; i++)
        #pragma unroll
        for (int j = 0; j < 8; j++) acc[i][j] = 0ull;

    const float* ap = in + r*68;
    const float* wp = W + j0*68;
    #pragma unroll 4
    for (int k = 0; k < 64; k += 4) {
        ulonglong2 a[4];
        a[0] = *(const ulonglong2*)(ap + k);
        a[1] = *(const ulonglong2*)(ap + 16*68 + k);
        a[2] = *(const ulonglong2*)(ap + 32*68 + k);
        a[3] = *(const ulonglong2*)(ap + 48*68 + k);
        #pragma unroll
        for (int j = 0; j < 8; j++) {
            ulonglong2 b = *(const ulonglong2*)(wp + j*8*68 + k);
            #pragma unroll
            for (int i = 0; i < 4; i++) {
                FMA2(acc[i][j], a[i].x, b.x);
                FMA2(acc[i][j], a[i].y, b.y);
            }
        }
    }
    #pragma unroll
    for (int j = 0; j < 8; j++) {
        int jj = j0 + 8*j;
        float bj = __ldg(bias + jj);
        #pragma unroll
        for (int i = 0; i < 4; i++) {
            int row = r + 16*i;
            float lo, hi; UNPK(lo, hi, acc[i][j]);
            og[jj*64 + row] = lo + hi + bj;
        }
    }
}

// splat a 10-float window into packed pairs
#define SPLAT10(XR, sp) { \
    float4 v0 = *(const float4*)(XR); \
    float4 v1 = *(const float4*)((XR)+4); \
    float2 v2 = *(const float2*)((XR)+8); \
    PK(sp[0],v0.x,v0.x); PK(sp[1],v0.y,v0.y); PK(sp[2],v0.z,v0.z); PK(sp[3],v0.w,v0.w); \
    PK(sp[4],v1.x,v1.x); PK(sp[5],v1.y,v1.y); PK(sp[6],v1.z,v1.z); PK(sp[7],v1.w,v1.w); \
    PK(sp[8],v2.x,v2.x); PK(sp[9],v2.y,v2.y); }

// conv channel-pair step: weights pre-paired (o2,o2+8) -> direct u64 operands
#define CONV_PAIR(XR0, XR1, WT) { \
    ulonglong2 L0 = __ldg((const ulonglong2*)(WT)); \
    ulonglong2 L1 = __ldg((const ulonglong2*)((WT)+4)); \
    ulonglong2 L2 = __ldg((const ulonglong2*)((WT)+8)); \
    u64 sp[10]; \
    SPLAT10(XR0, sp); \
    _Pragma("unroll") \
    for (int ii = 0; ii < 8; ii++) { \
        FMA2(a[ii], L0.x, sp[ii]); FMA2(a[ii], L0.y, sp[ii+1]); FMA2(a[ii], L1.x, sp[ii+2]); } \
    SPLAT10(XR1, sp); \
    _Pragma("unroll") \
    for (int ii = 0; ii < 8; ii++) { \
        FMA2(a[ii], L1.y, sp[ii]); FMA2(a[ii], L2.x, sp[ii+1]); FMA2(a[ii], L2.y, sp[ii+2]); } }

// ---------------- main fused kernel: one CTA per batch element ----------------
// smem (floats): X 0(4352) | CB 4352(4352) | T 8704(4352) | PF 13056(4352)
//                | W0 17408(4352) | W1 21760(4352; aliased as 4x Y1 during conv)
//                | LNS 26112(128)
#define SMEM_FLOATS 26240

__global__ void __launch_bounds__(NT, 2)
esa_main_kernel(const float* __restrict__ x,
                const float* __restrict__ conv1_b, const float* __restrict__ conv2_b,
                const float* __restrict__ pm1_w,  const float* __restrict__ pm2_b,
                const float* __restrict__ mo_w,   const float* __restrict__ mo_b,
                const float* __restrict__ out_w,  const float* __restrict__ out_b,
                const float* __restrict__ ln_g,   const float* __restrict__ ln_b,
                float* __restrict__ out)
{
    extern __shared__ float sm[];
    const int tid = threadIdx.x;
    const int b = blockIdx.x;
    float* X   = sm;
    float* CB  = sm + 4352;
    float* T   = sm + 8704;
    float* PF  = sm + 13056;
    float* W0  = sm + 17408;
    float* W1  = sm + 21760;
    float* LNS = sm + 26112;

    // ---- load x + stage pm1 into W0 + stage ln params ----
    {
        float4 pw[4]; pre_ld(pm1_w, 80, pw, tid);
        const float* xg = x + (size_t)b * 4096;
        for (int idx4 = tid; idx4 < 1024; idx4 += NT) {
            float4 v = __ldg((const float4*)xg + idx4);
            int c = idx4 >> 4, n = (idx4 & 15) << 2;
            float* rr = X + c*68 + 1 + n;
            rr[0] = v.x; rr[1] = v.y; rr[2] = v.z; rr[3] = v.w;
        }
        pre_st(W0, pw, tid);
        if (tid < 64) {
            X[tid*68] = 0.f;  X[tid*68 + 65] = 0.f;    // x pads
            W1[tid*68] = 0.f; W1[tid*68 + 65] = 0.f;   // Y1 pads (4 scales x 16 rows)
            LNS[tid]      = __ldg(ln_g + tid);
            LNS[64 + tid] = __ldg(ln_b + tid);
        }
    }
    __syncthreads();

    // ---- conv stack: 4 scales in one pass; thread = (s, o2, nq), 2 out-ch each ----
    {
        const int s  = tid >> 6;
        const int o2 = (tid >> 3) & 7;
        const int nq = tid & 7;
        const int base = nq * 8;
        float* Y1 = W1 + s*1088;
        {   // conv1: 64 -> 16 channels (channel pairs)
            const float* wt = g_cw1p + ((s*32)*8 + o2)*16;
            u64 a[8];
            #pragma unroll
            for (int j = 0; j < 8; j++) a[j] = 0ull;
            #pragma unroll 2
            for (int c2 = 0; c2 < 32; c2++)
                CONV_PAIR(X + (2*c2)*68 + base, X + (2*c2+1)*68 + base, wt + c2*128);
            float bb0 = __ldg(conv1_b + s*16 + o2);
            float bb1 = __ldg(conv1_b + s*16 + o2 + 8);
            float* y0 = Y1 + o2*68 + 1 + base;
            float* y1r = Y1 + (o2+8)*68 + 1 + base;
            #pragma unroll
            for (int j = 0; j < 8; j++) {
                float lo, hi; UNPK(lo, hi, a[j]);
                y0[j]  = fmaxf(lo+bb0, 0.f);
                y1r[j] = fmaxf(hi+bb1, 0.f);
            }
        }
        __syncthreads();
        {   // conv2: 16 -> 16 channels, swizzled transposed store into CB
            const float* wt = g_cw2p + ((s*8)*8 + o2)*16;
            u64 a[8];
            #pragma unroll
            for (int j = 0; j < 8; j++) a[j] = 0ull;
            #pragma unroll
            for (int c2 = 0; c2 < 8; c2++)
                CONV_PAIR(Y1 + (2*c2)*68 + base, Y1 + (2*c2+1)*68 + base, wt + c2*128);
            float bb0 = __ldg(conv2_b + s*16 + o2);
            float bb1 = __ldg(conv2_b + s*16 + o2 + 8);
            float olo[8], ohi[8];
            #pragma unroll
            for (int j = 0; j < 8; j++) UNPK(olo[j], ohi[j], a[j]);
            int ch0 = s*16 + o2, ch1 = ch0 + 8;
            #pragma unroll
            for (int ii = 0; ii < 8; ii++) {
                int rr = (ii + nq) & 7;     // bank-conflict-free rotation
                CB[(base+rr)*68 + ch0] = fmaxf(olo[rr]+bb0, 0.f);
                CB[(base+rr)*68 + ch1] = fmaxf(ohi[rr]+bb1, 0.f);
            }
        }
        __syncthreads();
    }

    // ---- P1: pm1 (W0): CB -> T (relu, P16 bias); stagers: mo -> W1 ----
    if (tid < 128) gemm48<true, true>(CB, 68, W0, g_p16, T, 68, tid);
    else stage_w_half(mo_w, W1, tid - 128);
    __syncthreads();

    // ---- P2: Q || K (pm2-folded, global k-major weights), all 8 warps ----
    if (tid < 128) gemm48g(T, 68, g_wqT, g_bq2, CB, 68, tid);       // Q -> CB
    else           gemm48g(T, 68, g_wkT, g_bk2, X,  68, tid - 128); // K -> X
    __syncthreads();

    // ---- P3: V || pm2, all 8 warps ----
    if (tid < 128) gemm48g(T, 68, g_wvT, g_bv2, PF, 68, tid);       // V  -> PF
    else           gemm48g(T, 68, g_pm2T, pm2_b, W0, 68, tid - 128);// pf -> W0
    __syncthreads();

    // ---- P4: attention (Q=CB, K=X, V=PF), exp2 (log2e folded into Q) ----
    {
        const int h8 = (tid >> 5) * 8;
        const int n0 = tid & 31;
        const float* q0p = CB + n0*68 + h8;
        const float* q1p = q0p + 32*68;
        ulonglong2 qa0 = *(const ulonglong2*)q0p;
        ulonglong2 qb0 = *(const ulonglong2*)(q0p + 4);
        ulonglong2 qa1 = *(const ulonglong2*)q1p;
        ulonglong2 qb1 = *(const ulonglong2*)(q1p + 4);
        float su0 = 0.f, su1 = 0.f;
        u64 c0[4] = {0ull,0ull,0ull,0ull};
        u64 c1[4] = {0ull,0ull,0ull,0ull};
        #pragma unroll 4
        for (int m = 0; m < 64; m++) {
            const float* kr = X  + m*68 + h8;
            const float* vr = PF + m*68 + h8;
            ulonglong2 ka = *(const ulonglong2*)kr;
            ulonglong2 kb = *(const ulonglong2*)(kr + 4);
            ulonglong2 va = *(const ulonglong2*)vr;
            ulonglong2 vb = *(const ulonglong2*)(vr + 4);
            u64 d0 = 0ull, d1 = 0ull;
            FMA2(d0, qa0.x, ka.x); FMA2(d0, qa0.y, ka.y);
            FMA2(d0, qb0.x, kb.x); FMA2(d0, qb0.y, kb.y);
            FMA2(d1, qa1.x, ka.x); FMA2(d1, qa1.y, ka.y);
            FMA2(d1, qb1.x, kb.x); FMA2(d1, qb1.y, kb.y);
            float lo, hi;
            UNPK(lo, hi, d0); float e0 = exp2f(lo + hi);
            UNPK(lo, hi, d1); float e1 = exp2f(lo + hi);
            su0 += e0; su1 += e1;
            u64 e0p, e1p;
            PK(e0p, e0, e0); PK(e1p, e1, e1);
            FMA2(c0[0], e0p, va.x); FMA2(c0[1], e0p, va.y);
            FMA2(c0[2], e0p, vb.x); FMA2(c0[3], e0p, vb.y);
            FMA2(c1[0], e1p, va.x); FMA2(c1[1], e1p, va.y);
            FMA2(c1[2], e1p, vb.x); FMA2(c1[3], e1p, vb.y);
        }
        float inv0 = 1.f / su0, inv1 = 1.f / su1;
        float w0l,w0h,w1l,w1h,w2l,w2h,w3l,w3h;
        UNPK(w0l,w0h,c0[0]); UNPK(w1l,w1h,c0[1]); UNPK(w2l,w2h,c0[2]); UNPK(w3l,w3h,c0[3]);
        *(float4*)(CB + n0*68 + h8)     = make_float4(w0l*inv0, w0h*inv0, w1l*inv0, w1h*inv0);
        *(float4*)(CB + n0*68 + h8 + 4) = make_float4(w2l*inv0, w2h*inv0, w3l*inv0, w3h*inv0);
        UNPK(w0l,w0h,c1[0]); UNPK(w1l,w1h,c1[1]); UNPK(w2l,w2h,c1[2]); UNPK(w3l,w3h,c1[3]);
        *(float4*)(CB + (n0+32)*68 + h8)     = make_float4(w0l*inv1, w0h*inv1, w1l*inv1, w1h*inv1);
        *(float4*)(CB + (n0+32)*68 + h8 + 4) = make_float4(w2l*inv1, w2h*inv1, w3l*inv1, w3h*inv1);
    }
    __syncthreads();

    // ---- P5: mo (W1) + geo + residual(pf=W0) + fused LN; stagers: out_w -> X ----
    if (tid < 128) gemm_mo_ln48(CB, W1, mo_b, W0, LNS, T, tid);
    else stage_w_half(out_w, X, tid - 128);
    __syncthreads();

    // ---- P6: final projection (X): T -> global, transposed layout ----
    if (tid < 128) gemm_out48(T, X, out_b, out + (size_t)b * 4096, tid);
}

// ---------------- launch ----------------
extern "C" void kernel_launch(void* const* d_in, const int* in_sizes, int n_in,
                              void* d_out, int out_size)
{
    const float* x         = (const float*)d_in[0];
    const float* points    = (const float*)d_in[1];
    const float* conv1_w   = (const float*)d_in[2];
    const float* conv1_b   = (const float*)d_in[3];
    const float* conv2_w   = (const float*)d_in[4];
    const float* conv2_b   = (const float*)d_in[5];
    const float* pattern   = (const float*)d_in[6];
    const float* pm1_w     = (const float*)d_in[7];
    const float* pm1_b     = (const float*)d_in[8];
    const float* pm2_w     = (const float*)d_in[9];
    const float* pm2_b     = (const float*)d_in[10];
    const float* q_w       = (const float*)d_in[11];
    const float* q_b       = (const float*)d_in[12];
    const float* k_w       = (const float*)d_in[13];
    const float* k_b       = (const float*)d_in[14];
    const float* v_w       = (const float*)d_in[15];
    const float* v_b       = (const float*)d_in[16];
    const float* in_w      = (const float*)d_in[17];
    const float* in_b      = (const float*)d_in[18];
    const float* mo_w      = (const float*)d_in[19];
    const float* mo_b      = (const float*)d_in[20];
    const float* out_w     = (const float*)d_in[21];
    const float* out_b     = (const float*)d_in[22];
    const float* ln_g      = (const float*)d_in[23];
    const float* ln_b      = (const float*)d_in[24];
    const int*   adjacency = (const int*)d_in[25];

    int B = in_sizes[0] / 4096;
    size_t smem = SMEM_FLOATS * sizeof(float);
    cudaFuncSetAttribute(esa_main_kernel, cudaFuncAttributeMaxDynamicSharedMemorySize, (int)smem);

    esa_prep_kernel<<<132, NT>>>(points, adjacency, in_w, in_b, pattern, pm1_w, pm1_b,
                                 conv1_w, conv2_w,
                                 q_w, q_b, k_w, k_b, v_w, v_b);
    esa_prep2_kernel<<<132, NT>>>(pm2_w, pm2_b);
    esa_main_kernel<<<B, NT, smem>>>(x, conv1_b, conv2_b,
                                     pm1_w, pm2_b, mo_w, mo_b,
                                     out_w, out_b, ln_g, ln_b, (float*)d_out);
}

// round 15
// speedup vs baseline: 1.0425x; 1.0369x over previous
#include <cuda_runtime.h>
#include <math.h>

#define NT 256
typedef unsigned long long u64;

// f32x2 packed math (Blackwell)
#define FMA2(d,a,b)  asm("fma.rn.f32x2 %0, %1, %2, %0;" : "+l"(d) : "l"(a), "l"(b))
#define UNPK(lo,hi,p) asm("mov.b64 {%0,%1}, %2;" : "=f"(lo), "=f"(hi) : "l"(p))
#define PK(p,lo,hi)   asm("mov.b64 %0, {%1,%2};" : "=l"(p) : "f"(lo), "f"(hi))

// ---------------- device scratch ----------------
__device__ __align__(16) float g_geo[4096];
__device__ __align__(16) float g_p16[4096];
// pm2-folded, k-major packed for 1-line global b-loads: [(kb*8+j)*32 + j0*4 + t]
__device__ __align__(16) float g_wqT[4096];
__device__ __align__(16) float g_wkT[4096];
__device__ __align__(16) float g_wvT[4096];
__device__ __align__(16) float g_pm2T[4096];
__device__ __align__(16) float g_bq2[64];
__device__ __align__(16) float g_bk2[64];
__device__ __align__(16) float g_bv2[64];
// conv weights, channel-pair records
__device__ __align__(16) float g_cw1p[16384];
__device__ __align__(16) float g_cw2p[4096];

// ---------------- single merged prep kernel ----------------
// blocks 0..47   : QKV double-fold chain, 4 rows per block (2-phase, smem-linked)
// blocks 48..131 : light gathers (geo, p16, conv packs, pm2T), grid-strided
__global__ void esa_prep_kernel(const float* __restrict__ points,
                                const int*   __restrict__ adjacency,
                                const float* __restrict__ in_w,
                                const float* __restrict__ in_b,
                                const float* __restrict__ pattern,
                                const float* __restrict__ pm1_w,
                                const float* __restrict__ pm1_b,
                                const float* __restrict__ conv1_w,
                                const float* __restrict__ conv2_w,
                                const float* __restrict__ pm2_w,
                                const float* __restrict__ pm2_b,
                                const float* __restrict__ q_w, const float* __restrict__ q_b,
                                const float* __restrict__ k_w, const float* __restrict__ k_b,
                                const float* __restrict__ v_w, const float* __restrict__ v_b)
{
    // 1/sqrt(8) * log2(e): fold softmax scale AND exp->exp2 conversion into Q
    const float scale = 0.3535533905932738f * 1.4426950408889634f;
    const int blk = blockIdx.x;
    const int tid = threadIdx.x;

    if (blk < 48) {
        // ---- W' = (in_w-slice @ xw) @ pm2_w, b' chain. 4 rows per block ----
        __shared__ float we[4][68];
        const int g  = tid >> 6;          // group 0..3
        const int lt = tid & 63;          // lane-in-group
        const int row = blk*4 + g;        // 0..191
        const int which = row >> 6;
        const int o = row & 63;
        const float* wi = in_w + which*4096 + o*64;
        const float* wx = (which==0) ? q_w : (which==1) ? k_w : v_w;
        // phase 1: we_row[lt] = wi . wx[:,lt]
        float s = 0.f;
        #pragma unroll 8
        for (int t = 0; t < 64; t++) s += __ldg(wi + t) * __ldg(wx + t*64 + lt);
        if (which == 0) s *= scale;
        we[g][lt] = s;
        __syncthreads();
        // phase 2: fold through pm2, write packed k-major record
        float acc = 0.f;
        #pragma unroll 8
        for (int u = 0; u < 64; u++) acc += we[g][u] * __ldg(pm2_w + u*64 + lt);
        int j0 = o & 7, jg = o >> 3;
        int kb = lt >> 2, t4 = lt & 3;
        float* dst = (which==0) ? g_wqT : (which==1) ? g_wkT : g_wvT;
        dst[kb*256 + jg*32 + j0*4 + t4] = acc;
        // bias chain (one lane per row)
        if (lt == 0) {
            const float* bx = (which==0) ? q_b : (which==1) ? k_b : v_b;
            float bb = __ldg(in_b + which*64 + o);
            #pragma unroll 8
            for (int t = 0; t < 64; t++) bb += __ldg(wi + t) * __ldg(bx + t);
            if (which == 0) bb *= scale;
            float b2 = bb;
            #pragma unroll 8
            for (int u = 0; u < 64; u++) b2 += we[g][u] * __ldg(pm2_b + u);
            float* bdst = (which==0) ? g_bq2 : (which==1) ? g_bk2 : g_bv2;
            bdst[o] = b2;
        }
        return;
    }

    // ---- light gathers ----
    const int gtid = (blk - 48) * NT + tid;
    const int gstride = (gridDim.x - 48) * NT;

    for (int idx = gtid; idx < 4096; idx += gstride) {
        int n = idx >> 6, m = idx & 63;
        float dx = points[n*3+0] - points[m*3+0];
        float dy = points[n*3+1] - points[m*3+1];
        float dz = points[n*3+2] - points[m*3+2];
        float dist = sqrtf(dx*dx + dy*dy + dz*dz + 1e-12f);
        g_geo[idx] = (adjacency[idx] > 0) ? 0.5f : (-0.1f / (1.0f + dist));
    }
    for (int idx = gtid; idx < 4096; idx += gstride) {
        int n = idx >> 6, j = idx & 63;
        float s = __ldg(pm1_b + j);
        const float* wr = pm1_w + j*80 + 64;
        const float* pr = pattern + n*16;
        #pragma unroll
        for (int p = 0; p < 16; p++) s += __ldg(pr + p) * __ldg(wr + p);
        g_p16[idx] = s;
    }
    for (int idx = gtid; idx < 16384; idx += gstride) {
        int j  = idx & 15;
        int o2 = (idx >> 4) & 7;
        int c2 = (idx >> 7) & 31;
        int s  = idx >> 12;
        float v = 0.f;
        if (j < 12) {
            int half = j / 6, jj = j % 6;
            int t = jj >> 1, hb = jj & 1;
            int c = 2*c2 + half;
            int o = o2 + 8*hb;
            v = __ldg(conv1_w + ((s*16 + o)*64 + c)*3 + t);
        }
        g_cw1p[idx] = v;
    }
    for (int idx = gtid; idx < 4096; idx += gstride) {
        int j  = idx & 15;
        int o2 = (idx >> 4) & 7;
        int c2 = (idx >> 7) & 7;
        int s  = idx >> 10;
        float v = 0.f;
        if (j < 12) {
            int half = j / 6, jj = j % 6;
            int t = jj >> 1, hb = jj & 1;
            int c = 2*c2 + half;
            int o = o2 + 8*hb;
            v = __ldg(conv2_w + ((s*16 + o)*16 + c)*3 + t);
        }
        g_cw2p[idx] = v;
    }
    for (int idx = gtid; idx < 4096; idx += gstride) {
        int t  = idx & 3;
        int j0 = (idx >> 2) & 7;
        int jg = (idx >> 5) & 7;
        int kb = idx >> 8;
        g_pm2T[idx] = __ldg(pm2_w + (j0 + 8*jg)*64 + kb*4 + t);
    }
}

// ---------------- weight staging ----------------
__device__ __forceinline__ void pre_ld(const float* __restrict__ src, int sstr,
                                       float4* r, int tid) {
    #pragma unroll
    for (int i = 0; i < 4; i++) {
        int idx4 = tid + i*NT;
        int rr = idx4 >> 4, cc = (idx4 & 15) << 2;
        r[i] = __ldg((const float4*)(src + rr*sstr + cc));
    }
}
__device__ __forceinline__ void pre_st(float* __restrict__ Wd, const float4* r, int tid) {
    #pragma unroll
    for (int i = 0; i < 4; i++) {
        int idx4 = tid + i*NT;
        int rr = idx4 >> 4, cc = (idx4 & 15) << 2;
        *(float4*)(Wd + rr*68 + cc) = r[i];
    }
}
__device__ __forceinline__ void stage_w_half(const float* __restrict__ src,
                                             float* __restrict__ Wd, int t2) {
    float4 r[8];
    #pragma unroll
    for (int i = 0; i < 8; i++) {
        int idx4 = t2 + i*128;
        int rr = idx4 >> 4, cc = (idx4 & 15) << 2;
        r[i] = __ldg((const float4*)(src + rr*64 + cc));
    }
    #pragma unroll
    for (int i = 0; i < 8; i++) {
        int idx4 = t2 + i*128;
        int rr = idx4 >> 4, cc = (idx4 & 15) << 2;
        *(float4*)(Wd + rr*68 + cc) = r[i];
    }
}

// ---------------- f32x2 GEMM, 4x8 tiles on 128 threads, smem weights ----------------
template<bool RELU, bool BIASMAT>
__device__ __forceinline__ void gemm48(const float* __restrict__ in, int sin,
                                       const float* __restrict__ W,
                                       const float* __restrict__ bias,
                                       float* __restrict__ outp, int so, int tid)
{
    const int r  = tid >> 3;
    const int j0 = tid & 7;
    u64 acc[4][8];
    #pragma unroll
    for (int i = 0; i < 4; i++)
        #pragma unroll
        for (int j = 0; j < 8; j++) acc[i][j] = 0ull;

    const float* ap = in + r*sin;
    const float* wp = W + j0*68;
    #pragma unroll 4
    for (int k = 0; k < 64; k += 4) {
        ulonglong2 a[4];
        a[0] = *(const ulonglong2*)(ap + k);
        a[1] = *(const ulonglong2*)(ap + 16*sin + k);
        a[2] = *(const ulonglong2*)(ap + 32*sin + k);
        a[3] = *(const ulonglong2*)(ap + 48*sin + k);
        #pragma unroll
        for (int j = 0; j < 8; j++) {
            ulonglong2 b = *(const ulonglong2*)(wp + j*8*68 + k);
            #pragma unroll
            for (int i = 0; i < 4; i++) {
                FMA2(acc[i][j], a[i].x, b.x);
                FMA2(acc[i][j], a[i].y, b.y);
            }
        }
    }
    #pragma unroll
    for (int j = 0; j < 8; j++) {
        int jj = j0 + 8*j;
        float bj = BIASMAT ? 0.f : __ldg(bias + jj);
        #pragma unroll
        for (int i = 0; i < 4; i++) {
            int row = r + 16*i;
            float lo, hi; UNPK(lo, hi, acc[i][j]);
            float v = lo + hi + bj;
            if (BIASMAT) v += __ldg(bias + row*64 + jj);
            if (RELU) v = fmaxf(v, 0.f);
            outp[row*so + jj] = v;
        }
    }
}

// ---------------- GEMM with k-major packed GLOBAL weights (1 line per load) ------
__device__ __forceinline__ void gemm48g(const float* __restrict__ in, int sin,
                                        const float* __restrict__ Wg,
                                        const float* __restrict__ bias,
                                        float* __restrict__ outp, int so, int t)
{
    const int r  = t >> 3;
    const int j0 = t & 7;
    u64 acc[4][8];
    #pragma unroll
    for (int i = 0; i < 4; i++)
        #pragma unroll
        for (int j = 0; j < 8; j++) acc[i][j] = 0ull;

    const float* ap = in + r*sin;
    const float* wp = Wg + j0*4;
    #pragma unroll 4
    for (int kb = 0; kb < 16; kb++) {
        int k = kb*4;
        ulonglong2 a[4];
        a[0] = *(const ulonglong2*)(ap + k);
        a[1] = *(const ulonglong2*)(ap + 16*sin + k);
        a[2] = *(const ulonglong2*)(ap + 32*sin + k);
        a[3] = *(const ulonglong2*)(ap + 48*sin + k);
        #pragma unroll
        for (int j = 0; j < 8; j++) {
            ulonglong2 b = __ldg((const ulonglong2*)(wp + (kb*8 + j)*32));
            #pragma unroll
            for (int i = 0; i < 4; i++) {
                FMA2(acc[i][j], a[i].x, b.x);
                FMA2(acc[i][j], a[i].y, b.y);
            }
        }
    }
    #pragma unroll
    for (int j = 0; j < 8; j++) {
        int jj = j0 + 8*j;
        float bj = __ldg(bias + jj);
        #pragma unroll
        for (int i = 0; i < 4; i++) {
            int row = r + 16*i;
            float lo, hi; UNPK(lo, hi, acc[i][j]);
            outp[row*so + jj] = lo + hi + bj;
        }
    }
}

// mo projection + geo + residual + FUSED LayerNorm
__device__ __forceinline__ void gemm_mo_ln48(const float* __restrict__ in,
                                             const float* __restrict__ W,
                                             const float* __restrict__ mo_b,
                                             const float* __restrict__ pf,
                                             const float* __restrict__ LNS,
                                             float* __restrict__ outp, int tid)
{
    const int r  = tid >> 3;
    const int j0 = tid & 7;
    u64 acc[4][8];
    #pragma unroll
    for (int i = 0; i < 4; i++)
        #pragma unroll
        for (int j = 0; j < 8; j++) acc[i][j] = 0ull;

    const float* ap = in + r*68;
    const float* wp = W + j0*68;
    #pragma unroll 4
    for (int k = 0; k < 64; k += 4) {
        ulonglong2 a[4];
        a[0] = *(const ulonglong2*)(ap + k);
        a[1] = *(const ulonglong2*)(ap + 16*68 + k);
        a[2] = *(const ulonglong2*)(ap + 32*68 + k);
        a[3] = *(const ulonglong2*)(ap + 48*68 + k);
        #pragma unroll
        for (int j = 0; j < 8; j++) {
            ulonglong2 b = *(const ulonglong2*)(wp + j*8*68 + k);
            #pragma unroll
            for (int i = 0; i < 4; i++) {
                FMA2(acc[i][j], a[i].x, b.x);
                FMA2(acc[i][j], a[i].y, b.y);
            }
        }
    }
    #pragma unroll
    for (int i = 0; i < 4; i++) {
        int row = r + 16*i;
        float v[8];
        float rs = 0.f, rq = 0.f;
        #pragma unroll
        for (int j = 0; j < 8; j++) {
            int jj = j0 + 8*j;
            float lo, hi; UNPK(lo, hi, acc[i][j]);
            float t = lo + hi + __ldg(mo_b + jj) + __ldg(g_geo + row*64 + jj)
                    + pf[row*68 + jj];
            v[j] = t; rs += t; rq += t*t;
        }
        rs += __shfl_xor_sync(0xffffffffu, rs, 1);
        rq += __shfl_xor_sync(0xffffffffu, rq, 1);
        rs += __shfl_xor_sync(0xffffffffu, rs, 2);
        rq += __shfl_xor_sync(0xffffffffu, rq, 2);
        rs += __shfl_xor_sync(0xffffffffu, rs, 4);
        rq += __shfl_xor_sync(0xffffffffu, rq, 4);
        float mu  = rs * 0.015625f;
        float var = rq * 0.015625f - mu*mu;
        float ri = rsqrtf(var + 1e-5f);
        #pragma unroll
        for (int j = 0; j < 8; j++) {
            int jj = j0 + 8*j;
            outp[row*68 + jj] = (v[j] - mu) * ri * LNS[jj] + LNS[64 + jj];
        }
    }
}

__device__ __forceinline__ void gemm_out48(const float* __restrict__ in,
                                           const float* __restrict__ W,
                                           const float* __restrict__ bias,
                                           float* __restrict__ og, int tid)
{
    const int r  = tid >> 3;
    const int j0 = tid & 7;
    u64 acc[4][8];
    #pragma unroll
    for (int i = 0; i < 4; i++)
        #pragma unroll
        for (int j = 0; j < 8; j++) acc[i][j] = 0ull;

    const float* ap = in + r*68;
    const float* wp = W + j0*68;
    #pragma unroll 4
    for (int k = 0; k < 64; k += 4) {
        ulonglong2 a[4];
        a[0] = *(const ulonglong2*)(ap + k);
        a[1] = *(const ulonglong2*)(ap + 16*68 + k);
        a[2] = *(const ulonglong2*)(ap + 32*68 + k);
        a[3] = *(const ulonglong2*)(ap + 48*68 + k);
        #pragma unroll
        for (int j = 0; j < 8; j++) {
            ulonglong2 b = *(const ulonglong2*)(wp + j*8*68 + k);
            #pragma unroll
            for (int i = 0; i < 4; i++) {
                FMA2(acc[i][j], a[i].x, b.x);
                FMA2(acc[i][j], a[i].y, b.y);
            }
        }
    }
    #pragma unroll
    for (int j = 0; j < 8; j++) {
        int jj = j0 + 8*j;
        float bj = __ldg(bias + jj);
        #pragma unroll
        for (int i = 0; i < 4; i++) {
            int row = r + 16*i;
            float lo, hi; UNPK(lo, hi, acc[i][j]);
            og[jj*64 + row] = lo + hi + bj;
        }
    }
}

// splat a 10-float window into packed pairs
#define SPLAT10(XR, sp) { \
    float4 v0 = *(const float4*)(XR); \
    float4 v1 = *(const float4*)((XR)+4); \
    float2 v2 = *(const float2*)((XR)+8); \
    PK(sp[0],v0.x,v0.x); PK(sp[1],v0.y,v0.y); PK(sp[2],v0.z,v0.z); PK(sp[3],v0.w,v0.w); \
    PK(sp[4],v1.x,v1.x); PK(sp[5],v1.y,v1.y); PK(sp[6],v1.z,v1.z); PK(sp[7],v1.w,v1.w); \
    PK(sp[8],v2.x,v2.x); PK(sp[9],v2.y,v2.y); }

// conv channel-pair step: weights pre-paired (o2,o2+8) -> direct u64 operands
#define CONV_PAIR(XR0, XR1, WT) { \
    ulonglong2 L0 = __ldg((const ulonglong2*)(WT)); \
    ulonglong2 L1 = __ldg((const ulonglong2*)((WT)+4)); \
    ulonglong2 L2 = __ldg((const ulonglong2*)((WT)+8)); \
    u64 sp[10]; \
    SPLAT10(XR0, sp); \
    _Pragma("unroll") \
    for (int ii = 0; ii < 8; ii++) { \
        FMA2(a[ii], L0.x, sp[ii]); FMA2(a[ii], L0.y, sp[ii+1]); FMA2(a[ii], L1.x, sp[ii+2]); } \
    SPLAT10(XR1, sp); \
    _Pragma("unroll") \
    for (int ii = 0; ii < 8; ii++) { \
        FMA2(a[ii], L1.y, sp[ii]); FMA2(a[ii], L2.x, sp[ii+1]); FMA2(a[ii], L2.y, sp[ii+2]); } }

// ---------------- main fused kernel: one CTA per batch element ----------------
// smem (floats): X 0(4352) | CB 4352(4352) | T 8704(4352) | PF 13056(4352)
//                | W0 17408(4352) | W1 21760(4352; aliased as 4x Y1 during conv)
//                | LNS 26112(128)
#define SMEM_FLOATS 26240

__global__ void __launch_bounds__(NT, 2)
esa_main_kernel(const float* __restrict__ x,
                const float* __restrict__ conv1_b, const float* __restrict__ conv2_b,
                const float* __restrict__ pm1_w,  const float* __restrict__ pm2_b,
                const float* __restrict__ mo_w,   const float* __restrict__ mo_b,
                const float* __restrict__ out_w,  const float* __restrict__ out_b,
                const float* __restrict__ ln_g,   const float* __restrict__ ln_b,
                float* __restrict__ out)
{
    extern __shared__ float sm[];
    const int tid = threadIdx.x;
    const int b = blockIdx.x;
    float* X   = sm;
    float* CB  = sm + 4352;
    float* T   = sm + 8704;
    float* PF  = sm + 13056;
    float* W0  = sm + 17408;
    float* W1  = sm + 21760;
    float* LNS = sm + 26112;

    // ---- load x + stage pm1 into W0 + stage ln params ----
    {
        float4 pw[4]; pre_ld(pm1_w, 80, pw, tid);
        const float* xg = x + (size_t)b * 4096;
        for (int idx4 = tid; idx4 < 1024; idx4 += NT) {
            float4 v = __ldg((const float4*)xg + idx4);
            int c = idx4 >> 4, n = (idx4 & 15) << 2;
            float* rr = X + c*68 + 1 + n;
            rr[0] = v.x; rr[1] = v.y; rr[2] = v.z; rr[3] = v.w;
        }
        pre_st(W0, pw, tid);
        if (tid < 64) {
            X[tid*68] = 0.f;  X[tid*68 + 65] = 0.f;    // x pads
            W1[tid*68] = 0.f; W1[tid*68 + 65] = 0.f;   // Y1 pads (4 scales x 16 rows)
            LNS[tid]      = __ldg(ln_g + tid);
            LNS[64 + tid] = __ldg(ln_b + tid);
        }
    }
    __syncthreads();

    // ---- conv stack: 4 scales in one pass; thread = (s, o2, nq), 2 out-ch each ----
    {
        const int s  = tid >> 6;
        const int o2 = (tid >> 3) & 7;
        const int nq = tid & 7;
        const int base = nq * 8;
        float* Y1 = W1 + s*1088;
        {   // conv1: 64 -> 16 channels (channel pairs)
            const float* wt = g_cw1p + ((s*32)*8 + o2)*16;
            u64 a[8];
            #pragma unroll
            for (int j = 0; j < 8; j++) a[j] = 0ull;
            #pragma unroll 2
            for (int c2 = 0; c2 < 32; c2++)
                CONV_PAIR(X + (2*c2)*68 + base, X + (2*c2+1)*68 + base, wt + c2*128);
            float bb0 = __ldg(conv1_b + s*16 + o2);
            float bb1 = __ldg(conv1_b + s*16 + o2 + 8);
            float* y0 = Y1 + o2*68 + 1 + base;
            float* y1r = Y1 + (o2+8)*68 + 1 + base;
            #pragma unroll
            for (int j = 0; j < 8; j++) {
                float lo, hi; UNPK(lo, hi, a[j]);
                y0[j]  = fmaxf(lo+bb0, 0.f);
                y1r[j] = fmaxf(hi+bb1, 0.f);
            }
        }
        __syncthreads();
        {   // conv2: 16 -> 16 channels, swizzled transposed store into CB
            const float* wt = g_cw2p + ((s*8)*8 + o2)*16;
            u64 a[8];
            #pragma unroll
            for (int j = 0; j < 8; j++) a[j] = 0ull;
            #pragma unroll
            for (int c2 = 0; c2 < 8; c2++)
                CONV_PAIR(Y1 + (2*c2)*68 + base, Y1 + (2*c2+1)*68 + base, wt + c2*128);
            float bb0 = __ldg(conv2_b + s*16 + o2);
            float bb1 = __ldg(conv2_b + s*16 + o2 + 8);
            float olo[8], ohi[8];
            #pragma unroll
            for (int j = 0; j < 8; j++) UNPK(olo[j], ohi[j], a[j]);
            int ch0 = s*16 + o2, ch1 = ch0 + 8;
            #pragma unroll
            for (int ii = 0; ii < 8; ii++) {
                int rr = (ii + nq) & 7;     // bank-conflict-free rotation
                CB[(base+rr)*68 + ch0] = fmaxf(olo[rr]+bb0, 0.f);
                CB[(base+rr)*68 + ch1] = fmaxf(ohi[rr]+bb1, 0.f);
            }
        }
        __syncthreads();
    }

    // ---- P1: pm1 (W0): CB -> T (relu, P16 bias); stagers: mo -> W1 ----
    if (tid < 128) gemm48<true, true>(CB, 68, W0, g_p16, T, 68, tid);
    else stage_w_half(mo_w, W1, tid - 128);
    __syncthreads();

    // ---- P2: Q || K (pm2-folded, global k-major weights), all 8 warps ----
    if (tid < 128) gemm48g(T, 68, g_wqT, g_bq2, CB, 68, tid);       // Q -> CB
    else           gemm48g(T, 68, g_wkT, g_bk2, X,  68, tid - 128); // K -> X
    __syncthreads();

    // ---- P3: V || pm2, all 8 warps ----
    if (tid < 128) gemm48g(T, 68, g_wvT, g_bv2, PF, 68, tid);       // V  -> PF
    else           gemm48g(T, 68, g_pm2T, pm2_b, W0, 68, tid - 128);// pf -> W0
    __syncthreads();

    // ---- P4: attention (Q=CB, K=X, V=PF), exp2 (log2e folded into Q) ----
    {
        const int h8 = (tid >> 5) * 8;
        const int n0 = tid & 31;
        const float* q0p = CB + n0*68 + h8;
        const float* q1p = q0p + 32*68;
        ulonglong2 qa0 = *(const ulonglong2*)q0p;
        ulonglong2 qb0 = *(const ulonglong2*)(q0p + 4);
        ulonglong2 qa1 = *(const ulonglong2*)q1p;
        ulonglong2 qb1 = *(const ulonglong2*)(q1p + 4);
        float su0 = 0.f, su1 = 0.f;
        u64 c0[4] = {0ull,0ull,0ull,0ull};
        u64 c1[4] = {0ull,0ull,0ull,0ull};
        #pragma unroll 4
        for (int m = 0; m < 64; m++) {
            const float* kr = X  + m*68 + h8;
            const float* vr = PF + m*68 + h8;
            ulonglong2 ka = *(const ulonglong2*)kr;
            ulonglong2 kb = *(const ulonglong2*)(kr + 4);
            ulonglong2 va = *(const ulonglong2*)vr;
            ulonglong2 vb = *(const ulonglong2*)(vr + 4);
            u64 d0 = 0ull, d1 = 0ull;
            FMA2(d0, qa0.x, ka.x); FMA2(d0, qa0.y, ka.y);
            FMA2(d0, qb0.x, kb.x); FMA2(d0, qb0.y, kb.y);
            FMA2(d1, qa1.x, ka.x); FMA2(d1, qa1.y, ka.y);
            FMA2(d1, qb1.x, kb.x); FMA2(d1, qb1.y, kb.y);
            float lo, hi;
            UNPK(lo, hi, d0); float e0 = exp2f(lo + hi);
            UNPK(lo, hi, d1); float e1 = exp2f(lo + hi);
            su0 += e0; su1 += e1;
            u64 e0p, e1p;
            PK(e0p, e0, e0); PK(e1p, e1, e1);
            FMA2(c0[0], e0p, va.x); FMA2(c0[1], e0p, va.y);
            FMA2(c0[2], e0p, vb.x); FMA2(c0[3], e0p, vb.y);
            FMA2(c1[0], e1p, va.x); FMA2(c1[1], e1p, va.y);
            FMA2(c1[2], e1p, vb.x); FMA2(c1[3], e1p, vb.y);
        }
        float inv0 = 1.f / su0, inv1 = 1.f / su1;
        float w0l,w0h,w1l,w1h,w2l,w2h,w3l,w3h;
        UNPK(w0l,w0h,c0[0]); UNPK(w1l,w1h,c0[1]); UNPK(w2l,w2h,c0[2]); UNPK(w3l,w3h,c0[3]);
        *(float4*)(CB + n0*68 + h8)     = make_float4(w0l*inv0, w0h*inv0, w1l*inv0, w1h*inv0);
        *(float4*)(CB + n0*68 + h8 + 4) = make_float4(w2l*inv0, w2h*inv0, w3l*inv0, w3h*inv0);
        UNPK(w0l,w0h,c1[0]); UNPK(w1l,w1h,c1[1]); UNPK(w2l,w2h,c1[2]); UNPK(w3l,w3h,c1[3]);
        *(float4*)(CB + (n0+32)*68 + h8)     = make_float4(w0l*inv1, w0h*inv1, w1l*inv1, w1h*inv1);
        *(float4*)(CB + (n0+32)*68 + h8 + 4) = make_float4(w2l*inv1, w2h*inv1, w3l*inv1, w3h*inv1);
    }
    __syncthreads();

    // ---- P5: mo (W1) + geo + residual(pf=W0) + fused LN; stagers: out_w -> X ----
    if (tid < 128) gemm_mo_ln48(CB, W1, mo_b, W0, LNS, T, tid);
    else stage_w_half(out_w, X, tid - 128);
    __syncthreads();

    // ---- P6: final projection (X): T -> global, transposed layout ----
    if (tid < 128) gemm_out48(T, X, out_b, out + (size_t)b * 4096, tid);
}

// ---------------- launch ----------------
extern "C" void kernel_launch(void* const* d_in, const int* in_sizes, int n_in,
                              void* d_out, int out_size)
{
    const float* x         = (const float*)d_in[0];
    const float* points    = (const float*)d_in[1];
    const float* conv1_w   = (const float*)d_in[2];
    const float* conv1_b   = (const float*)d_in[3];
    const float* conv2_w   = (const float*)d_in[4];
    const float* conv2_b   = (const float*)d_in[5];
    const float* pattern   = (const float*)d_in[6];
    const float* pm1_w     = (const float*)d_in[7];
    const float* pm1_b     = (const float*)d_in[8];
    const float* pm2_w     = (const float*)d_in[9];
    const float* pm2_b     = (const float*)d_in[10];
    const float* q_w       = (const float*)d_in[11];
    const float* q_b       = (const float*)d_in[12];
    const float* k_w       = (const float*)d_in[13];
    const float* k_b       = (const float*)d_in[14];
    const float* v_w       = (const float*)d_in[15];
    const float* v_b       = (const float*)d_in[16];
    const float* in_w      = (const float*)d_in[17];
    const float* in_b      = (const float*)d_in[18];
    const float* mo_w      = (const float*)d_in[19];
    const float* mo_b      = (const float*)d_in[20];
    const float* out_w     = (const float*)d_in[21];
    const float* out_b     = (const float*)d_in[22];
    const float* ln_g      = (const float*)d_in[23];
    const float* ln_b      = (const float*)d_in[24];
    const int*   adjacency = (const int*)d_in[25];

    int B = in_sizes[0] / 4096;
    size_t smem = SMEM_FLOATS * sizeof(float);
    cudaFuncSetAttribute(esa_main_kernel, cudaFuncAttributeMaxDynamicSharedMemorySize, (int)smem);

    esa_prep_kernel<<<132, NT>>>(points, adjacency, in_w, in_b, pattern, pm1_w, pm1_b,
                                 conv1_w, conv2_w, pm2_w, pm2_b,
                                 q_w, q_b, k_w, k_b, v_w, v_b);
    esa_main_kernel<<<B, NT, smem>>>(x, conv1_b, conv2_b,
                                     pm1_w, pm2_b, mo_w, mo_b,
                                     out_w, out_b, ln_g, ln_b, (float*)d_out);
}